// round 2
// baseline (speedup 1.0000x reference)
#include <cuda_runtime.h>
#include <cuda_bf16.h>
#include <cstdint>
#include <cstdio>

// Problem constants
#define BB 256
#define TT 512
#define NN 128

// ---------------- device scratch (statics: allowed) ----------------
__device__ float g_E[NN * NN];        // exp(trans)
__device__ float g_transT[NN * NN];   // trans transposed: transT[j][i] = trans[i][j]
__device__ float g_score[BB];         // sequence scores
__device__ float g_alpha[(size_t)BB * TT * NN]; // viterbi alphas, 64 MB
__device__ int   g_lasttag[BB];

__device__ __forceinline__ unsigned ordf(float f) {
    unsigned u = __float_as_uint(f);
    return u ^ (((int)u >> 31) | 0x80000000u);
}

// ---------------- K0: prep -----------------------------------------
__global__ void k_prep(const float* __restrict__ trans, float* __restrict__ out_trans) {
    int idx = blockIdx.x * 256 + threadIdx.x;
    if (idx < NN * NN) {
        float v = trans[idx];
        g_E[idx] = __expf(v);
        int i = idx >> 7, j = idx & 127;
        g_transT[j * NN + i] = v;
        out_trans[idx] = v;
    }
}

// ---------------- K1: sequence score --------------------------------
// NOTE: tag_ids declared int64 in the reference, but JAX (x64 disabled)
// silently produces int32 — read as int.
__global__ __launch_bounds__(256) void k_score(const float* __restrict__ emis,
                                               const int* __restrict__ tags,
                                               const int* __restrict__ mask,
                                               const float* __restrict__ trans) {
    __shared__ float sred[8];
    const int b = blockIdx.x;
    const int tid = threadIdx.x;
    float acc = 0.f;
    const float* eb = emis + (size_t)b * TT * NN;
    const int* tb = tags + (size_t)b * TT;
    const int* mb = mask + (size_t)b * TT;
    for (int t = tid; t < TT; t += 256) {
        int tg = tb[t];
        float mf = (float)mb[t];
        float u = eb[(size_t)t * NN + tg] * mf;
        float bi = 0.f;
        if (t > 0) {
            int tp = tb[t - 1];
            bi = trans[tp * NN + tg] * mf;
        }
        acc += u + bi;
    }
    #pragma unroll
    for (int o = 16; o; o >>= 1) acc += __shfl_xor_sync(0xffffffffu, acc, o);
    if ((tid & 31) == 0) sred[tid >> 5] = acc;
    __syncthreads();
    if (tid == 0) {
        float s = 0.f;
        #pragma unroll
        for (int i = 0; i < 8; i++) s += sred[i];
        g_score[b] = s;
    }
}

// ---------------- K2: log-norm forward (FFMA matvec) -----------------
// 256 threads: h = tid>>7 (half of i-range), j = tid&127 (state column).
// Thread holds E[i][j] for i in [h*64, h*64+64) in registers.
__global__ __launch_bounds__(256, 2) void k_forward(const float* __restrict__ emis,
                                                    const int* __restrict__ mask,
                                                    float* __restrict__ out_ll) {
    const int b = blockIdx.x;
    const int tid = threadIdx.x;
    const int h = tid >> 7;
    const int j = tid & 127;

    __shared__ float p[2][NN];
    __shared__ float psum[NN];
    __shared__ float csm;
    __shared__ float sred[8];

    float Ereg[64];
    {
        const float* Eb = g_E + (size_t)(h * 64) * NN + j;
        #pragma unroll
        for (int k = 0; k < 64; k++) Ereg[k] = Eb[(size_t)k * NN];
    }

    const float* eb = emis + (size_t)b * TT * NN;
    const int* mb = mask + (size_t)b * TT;

    float a = eb[j];   // alpha_0 (meaningful for h==0)
    float c = 0.f;

    float e_next = 0.f; int m_next = 1;
    if (h == 0) { e_next = eb[NN + j]; m_next = mb[1]; }

    for (int t = 1; t < TT; t++) {
        if (((t - 1) & 3) == 0) {          // renormalize every 4 steps
            if (tid == 0) csm = a;
            __syncthreads();
            c = csm;
        }
        const int sel = t & 1;
        if (h == 0) p[sel][j] = __expf(a - c);
        __syncthreads();

        float e_cur = e_next; int m_cur = m_next;
        if (h == 0 && t + 1 < TT) { e_next = eb[(size_t)(t + 1) * NN + j]; m_next = mb[t + 1]; }

        float s0 = 0.f, s1 = 0.f, s2 = 0.f, s3 = 0.f;
        const float4* pv = (const float4*)(p[sel] + h * 64);
        #pragma unroll
        for (int k = 0; k < 16; k++) {
            float4 v = pv[k];
            s0 += v.x * Ereg[4 * k + 0];
            s1 += v.y * Ereg[4 * k + 1];
            s2 += v.z * Ereg[4 * k + 2];
            s3 += v.w * Ereg[4 * k + 3];
        }
        float s = (s0 + s1) + (s2 + s3);
        if (h == 1) psum[j] = s;
        __syncthreads();
        if (h == 0) {
            float st = s + psum[j];
            float anew = __logf(st) + c + e_cur;
            a = m_cur ? anew : a;
        }
    }

    // final logsumexp over alpha (h==0 threads hold it)
    float term = (h == 0) ? __expf(a - c) : 0.f;
    #pragma unroll
    for (int o = 16; o; o >>= 1) term += __shfl_xor_sync(0xffffffffu, term, o);
    if ((tid & 31) == 0) sred[tid >> 5] = term;
    __syncthreads();
    if (tid == 0) {
        float tot = 0.f;
        #pragma unroll
        for (int i = 0; i < 8; i++) tot += sred[i];
        float log_norm = __logf(tot) + c;
        out_ll[b] = g_score[b] - log_norm;
    }
}

// ---------------- K3: viterbi forward (max-plus, store alphas) -------
__global__ __launch_bounds__(256, 2) void k_viterbi(const float* __restrict__ emis,
                                                    const int* __restrict__ mask,
                                                    const float* __restrict__ trans) {
    const int b = blockIdx.x;
    const int tid = threadIdx.x;
    const int h = tid >> 7;
    const int j = tid & 127;

    __shared__ float al[NN];
    __shared__ float v1[NN];

    float Treg[64];
    {
        const float* Tb = trans + (size_t)(h * 64) * NN + j;
        #pragma unroll
        for (int k = 0; k < 64; k++) Treg[k] = Tb[(size_t)k * NN];
    }

    const float* eb = emis + (size_t)b * TT * NN;
    const int* mb = mask + (size_t)b * TT;
    float* arow = g_alpha + (size_t)b * TT * NN;

    if (h == 0) {
        float a0 = eb[j];
        al[j] = a0;
        arow[j] = a0;
    }
    float e_next = 0.f; int m_next = 1;
    if (h == 0) { e_next = eb[NN + j]; m_next = mb[1]; }

    const float NEGINF = -3.402823466e38f;

    for (int t = 1; t < TT; t++) {
        __syncthreads();  // al ready
        float b0 = NEGINF, b1 = NEGINF, b2 = NEGINF, b3 = NEGINF;
        const float4* av = (const float4*)(al + h * 64);
        #pragma unroll
        for (int k = 0; k < 16; k++) {
            float4 v = av[k];
            b0 = fmaxf(b0, v.x + Treg[4 * k + 0]);
            b1 = fmaxf(b1, v.y + Treg[4 * k + 1]);
            b2 = fmaxf(b2, v.z + Treg[4 * k + 2]);
            b3 = fmaxf(b3, v.w + Treg[4 * k + 3]);
        }
        float bm = fmaxf(fmaxf(b0, b1), fmaxf(b2, b3));
        if (h == 1) v1[j] = bm;
        __syncthreads();

        float e_cur = e_next; int m_cur = m_next;
        if (h == 0 && t + 1 < TT) { e_next = eb[(size_t)(t + 1) * NN + j]; m_next = mb[t + 1]; }

        if (h == 0) {
            float m = fmaxf(bm, v1[j]);
            float anew = m + e_cur;
            float aold = al[j];
            float aout = m_cur ? anew : aold;
            al[j] = aout;
            arow[(size_t)t * NN + j] = aout;
        }
    }

    __syncthreads();
    // last_tag = first argmax over al (warp 0, lane l owns i = 4l..4l+3)
    if (tid < 32) {
        float4 v = ((const float4*)al)[tid];
        float best = v.x; int bi = 4 * tid;
        if (v.y > best) { best = v.y; bi = 4 * tid + 1; }
        if (v.z > best) { best = v.z; bi = 4 * tid + 2; }
        if (v.w > best) { best = v.w; bi = 4 * tid + 3; }
        unsigned u = ordf(best);
        unsigned wm = __reduce_max_sync(0xffffffffu, u);
        unsigned bal = __ballot_sync(0xffffffffu, u == wm);
        int src = __ffs(bal) - 1;
        bi = __shfl_sync(0xffffffffu, bi, src);
        if (tid == 0) g_lasttag[b] = bi;
    }
}

// ---------------- K4: traceback (argmax recompute along path) --------
// 32 blocks x 256 threads; warp w of block handles batch blockIdx.x*8+w.
// transT cached in 64KB dynamic smem.
__global__ void k_traceback(const int* __restrict__ mask, float* __restrict__ out_tags) {
    extern __shared__ float sT[]; // transT[128][128]
    for (int idx = threadIdx.x; idx < NN * NN; idx += 256) sT[idx] = g_transT[idx];
    __syncthreads();

    const int w = threadIdx.x >> 5;
    const int l = threadIdx.x & 31;
    const int b = blockIdx.x * 8 + w;

    const float* arows = g_alpha + (size_t)b * TT * NN;
    const int* mb = mask + (size_t)b * TT;
    float* ot = out_tags + (size_t)b * TT;

    int tag = g_lasttag[b];
    if (l == 0) ot[TT - 1] = (float)tag;

    float4 A_next = ((const float4*)(arows + (size_t)(TT - 2) * NN))[l];
    int m_next = mb[TT - 1];

    for (int t = TT - 2; t >= 0; t--) {
        float4 A = A_next; int m_cur = m_next;
        if (t > 0) {
            A_next = ((const float4*)(arows + (size_t)(t - 1) * NN))[l];
            m_next = mb[t];
        }
        if (m_cur) {
            float4 Tv = ((const float4*)(sT + (size_t)tag * NN))[l];
            float v0 = A.x + Tv.x, vv1 = A.y + Tv.y, v2 = A.z + Tv.z, v3 = A.w + Tv.w;
            float best = v0; int bi = 4 * l;
            if (vv1 > best) { best = vv1; bi = 4 * l + 1; }
            if (v2 > best)  { best = v2;  bi = 4 * l + 2; }
            if (v3 > best)  { best = v3;  bi = 4 * l + 3; }
            unsigned u = ordf(best);
            unsigned wm = __reduce_max_sync(0xffffffffu, u);
            unsigned bal = __ballot_sync(0xffffffffu, u == wm);
            int src = __ffs(bal) - 1;
            tag = __shfl_sync(0xffffffffu, bi, src);
        }
        if (l == 0) ot[t] = (float)tag;
    }
}

// ---------------- launch ---------------------------------------------
extern "C" void kernel_launch(void* const* d_in, const int* in_sizes, int n_in,
                              void* d_out, int out_size) {
    const float* emis  = (const float*)d_in[0];
    const int*   tags  = (const int*)d_in[1];
    const int*   mask  = (const int*)d_in[2];
    const float* trans = (const float*)d_in[3];
    float* out = (float*)d_out;

    // out layout: [0,256) ll | [256, 256+16384) trans | [16640, 147712) tags
    float* out_ll    = out;
    float* out_trans = out + BB;
    float* out_tags  = out + BB + NN * NN;

    cudaFuncSetAttribute(k_traceback, cudaFuncAttributeMaxDynamicSharedMemorySize,
                         NN * NN * (int)sizeof(float));

    k_prep<<<(NN * NN + 255) / 256, 256>>>(trans, out_trans);
    k_score<<<BB, 256>>>(emis, tags, mask, trans);
    k_forward<<<BB, 256>>>(emis, mask, out_ll);
    k_viterbi<<<BB, 256>>>(emis, mask, trans);
    k_traceback<<<BB / 8, 256, NN * NN * (int)sizeof(float)>>>(mask, out_tags);
}

// round 3
// speedup vs baseline: 1.0952x; 1.0952x over previous
#include <cuda_runtime.h>
#include <cuda_bf16.h>
#include <cstdint>

// Problem constants
#define BB 256
#define TT 512
#define NN 128

// ---------------- device scratch ----------------
__device__ float g_E[NN * NN];        // exp(trans)
__device__ float g_transT[NN * NN];   // transT[j][i] = trans[i][j]
__device__ float g_score[BB];
__device__ float g_alpha[(size_t)BB * TT * NN]; // viterbi alphas, 64 MB
__device__ int   g_lasttag[BB];

__device__ __forceinline__ unsigned ordf(float f) {
    unsigned u = __float_as_uint(f);
    return u ^ (((int)u >> 31) | 0x80000000u);
}

__device__ __forceinline__ void ffma2(unsigned long long& d,
                                      unsigned long long a,
                                      unsigned long long b) {
    asm("fma.rn.f32x2 %0, %1, %2, %0;" : "+l"(d) : "l"(a), "l"(b));
}

__device__ __forceinline__ float lo32(unsigned long long v) {
    return __uint_as_float((unsigned)v);
}
__device__ __forceinline__ float hi32(unsigned long long v) {
    return __uint_as_float((unsigned)(v >> 32));
}

// ---------------- K0: prep -----------------------------------------
__global__ void k_prep(const float* __restrict__ trans, float* __restrict__ out_trans) {
    int idx = blockIdx.x * 256 + threadIdx.x;
    if (idx < NN * NN) {
        float v = trans[idx];
        g_E[idx] = __expf(v);
        int i = idx >> 7, j = idx & 127;
        g_transT[j * NN + i] = v;
        out_trans[idx] = v;
    }
}

// ---------------- K1: sequence score --------------------------------
// tag_ids: JAX silently emits int32 despite int64 declaration.
__global__ __launch_bounds__(256) void k_score(const float* __restrict__ emis,
                                               const int* __restrict__ tags,
                                               const int* __restrict__ mask,
                                               const float* __restrict__ trans) {
    __shared__ float sred[8];
    const int b = blockIdx.x;
    const int tid = threadIdx.x;
    float acc = 0.f;
    const float* eb = emis + (size_t)b * TT * NN;
    const int* tb = tags + (size_t)b * TT;
    const int* mb = mask + (size_t)b * TT;
    for (int t = tid; t < TT; t += 256) {
        int tg = tb[t];
        float mf = (float)mb[t];
        float u = eb[(size_t)t * NN + tg] * mf;
        float bi = 0.f;
        if (t > 0) {
            int tp = tb[t - 1];
            bi = trans[tp * NN + tg] * mf;
        }
        acc += u + bi;
    }
    #pragma unroll
    for (int o = 16; o; o >>= 1) acc += __shfl_xor_sync(0xffffffffu, acc, o);
    if ((tid & 31) == 0) sred[tid >> 5] = acc;
    __syncthreads();
    if (tid == 0) {
        float s = 0.f;
        #pragma unroll
        for (int i = 0; i < 8; i++) s += sred[i];
        g_score[b] = s;
    }
}

// ---------------- K2: fused recurrences ------------------------------
// grid = 512. blockIdx&1 == 0 -> forward (log-norm), == 1 -> viterbi.
// 128 threads; thread j owns output state j and the full matrix column in
// registers. One __syncthreads() per time step (double-buffered alpha bcast).
__global__ __launch_bounds__(128, 2) void k_recur(const float* __restrict__ emis,
                                                  const int* __restrict__ mask,
                                                  const float* __restrict__ trans,
                                                  float* __restrict__ out_ll) {
    const int type = blockIdx.x & 1;
    const int b = blockIdx.x >> 1;
    const int j = threadIdx.x;

    __shared__ __align__(16) float buf[2][NN];
    __shared__ float csm[2];
    __shared__ int smask[TT];

    const float* eb = emis + (size_t)b * TT * NN;
    const int* mb = mask + (size_t)b * TT;

    for (int i = j; i < TT; i += NN) smask[i] = mb[i];

    if (type == 0) {
        // ---------------- forward: alpha'_j = log(sum_i p_i * E_ij) + c + e
        unsigned long long E2[64];
        {
            const float* Ej = g_E + j;
            #pragma unroll
            for (int k = 0; k < 64; k++) {
                unsigned lo = __float_as_uint(Ej[(size_t)(2 * k) * NN]);
                unsigned hi = __float_as_uint(Ej[(size_t)(2 * k + 1) * NN]);
                E2[k] = (unsigned long long)lo | ((unsigned long long)hi << 32);
            }
        }

        float a = eb[j];
        float c = eb[0];             // broadcast-ish scale; exact value irrelevant
        float e_next = eb[NN + j];
        int sel = 0;
        __syncthreads();             // smask ready

        for (int t = 1; t < TT; t++) {
            buf[sel][j] = __expf(a - c);
            if (j == 0) csm[sel] = a;
            __syncthreads();
            float c_next = csm[sel];

            unsigned long long acc[8];
            #pragma unroll
            for (int q = 0; q < 8; q++) acc[q] = 0ull;
            const ulonglong2* pv = (const ulonglong2*)buf[sel];
            #pragma unroll
            for (int k = 0; k < 32; k++) {
                ulonglong2 v = pv[k];
                ffma2(acc[(2 * k) & 7], v.x, E2[2 * k]);
                ffma2(acc[(2 * k + 1) & 7], v.y, E2[2 * k + 1]);
            }
            float s = 0.f;
            #pragma unroll
            for (int q = 0; q < 8; q++) s += lo32(acc[q]) + hi32(acc[q]);

            float e_cur = e_next;
            if (t + 1 < TT) e_next = eb[(size_t)(t + 1) * NN + j];

            float a_new = __logf(s) + c + e_cur;
            a = smask[t] ? a_new : a;
            c = c_next;
            sel ^= 1;
        }

        // final logsumexp
        buf[0][j] = __expf(a - c);
        __syncthreads();
        if (j < 32) {
            float4 v = ((const float4*)buf[0])[j];
            float tsum = (v.x + v.y) + (v.z + v.w);
            #pragma unroll
            for (int o = 16; o; o >>= 1) tsum += __shfl_xor_sync(0xffffffffu, tsum, o);
            if (j == 0) out_ll[b] = g_score[b] - (__logf(tsum) + c);
        }
    } else {
        // ---------------- viterbi: alpha'_j = max_i(a_i + T_ij) + e
        float T[128];
        {
            const float* Tj = trans + j;
            #pragma unroll
            for (int k = 0; k < 128; k++) T[k] = Tj[(size_t)k * NN];
        }

        float* arow = g_alpha + (size_t)b * TT * NN;
        float a = eb[j];
        buf[0][j] = a;
        arow[j] = a;
        float e_next = eb[NN + j];
        int sel = 0;
        const float NEGINF = -3.402823466e38f;
        __syncthreads();             // buf[0] + smask ready

        for (int t = 1; t < TT; t++) {
            float m[8];
            #pragma unroll
            for (int q = 0; q < 8; q++) m[q] = NEGINF;
            const float4* av = (const float4*)buf[sel];
            #pragma unroll
            for (int k = 0; k < 32; k++) {
                float4 v = av[k];
                int q = (4 * k) & 7;
                m[q + 0] = fmaxf(m[q + 0], v.x + T[4 * k + 0]);
                m[q + 1] = fmaxf(m[q + 1], v.y + T[4 * k + 1]);
                m[q + 2] = fmaxf(m[q + 2], v.z + T[4 * k + 2]);
                m[q + 3] = fmaxf(m[q + 3], v.w + T[4 * k + 3]);
            }
            float bm = fmaxf(fmaxf(fmaxf(m[0], m[1]), fmaxf(m[2], m[3])),
                             fmaxf(fmaxf(m[4], m[5]), fmaxf(m[6], m[7])));

            float e_cur = e_next;
            if (t + 1 < TT) e_next = eb[(size_t)(t + 1) * NN + j];

            float a_new = bm + e_cur;
            a = smask[t] ? a_new : a;
            buf[sel ^ 1][j] = a;
            arow[(size_t)t * NN + j] = a;
            sel ^= 1;
            __syncthreads();
        }

        // last_tag = first argmax over final alphas (in buf[sel])
        if (j < 32) {
            float4 v = ((const float4*)buf[sel])[j];
            float best = v.x; int bi = 4 * j;
            if (v.y > best) { best = v.y; bi = 4 * j + 1; }
            if (v.z > best) { best = v.z; bi = 4 * j + 2; }
            if (v.w > best) { best = v.w; bi = 4 * j + 3; }
            unsigned u = ordf(best);
            unsigned wm = __reduce_max_sync(0xffffffffu, u);
            unsigned bal = __ballot_sync(0xffffffffu, u == wm);
            int src = __ffs(bal) - 1;
            bi = __shfl_sync(0xffffffffu, bi, src);
            if (j == 0) g_lasttag[b] = bi;
        }
    }
}

// ---------------- K4: traceback --------------------------------------
__global__ void k_traceback(const int* __restrict__ mask, float* __restrict__ out_tags) {
    extern __shared__ float sT[]; // transT[128][128]
    for (int idx = threadIdx.x; idx < NN * NN; idx += 256) sT[idx] = g_transT[idx];
    __syncthreads();

    const int w = threadIdx.x >> 5;
    const int l = threadIdx.x & 31;
    const int b = blockIdx.x * 8 + w;

    const float* arows = g_alpha + (size_t)b * TT * NN;
    const int* mb = mask + (size_t)b * TT;
    float* ot = out_tags + (size_t)b * TT;

    int tag = g_lasttag[b];
    if (l == 0) ot[TT - 1] = (float)tag;

    float4 A_next = ((const float4*)(arows + (size_t)(TT - 2) * NN))[l];
    int m_next = mb[TT - 1];

    for (int t = TT - 2; t >= 0; t--) {
        float4 A = A_next; int m_cur = m_next;
        if (t > 0) {
            A_next = ((const float4*)(arows + (size_t)(t - 1) * NN))[l];
            m_next = mb[t];
        }
        if (m_cur) {
            float4 Tv = ((const float4*)(sT + (size_t)tag * NN))[l];
            float v0 = A.x + Tv.x, vv1 = A.y + Tv.y, v2 = A.z + Tv.z, v3 = A.w + Tv.w;
            float best = v0; int bi = 4 * l;
            if (vv1 > best) { best = vv1; bi = 4 * l + 1; }
            if (v2 > best)  { best = v2;  bi = 4 * l + 2; }
            if (v3 > best)  { best = v3;  bi = 4 * l + 3; }
            unsigned u = ordf(best);
            unsigned wm = __reduce_max_sync(0xffffffffu, u);
            unsigned bal = __ballot_sync(0xffffffffu, u == wm);
            int src = __ffs(bal) - 1;
            tag = __shfl_sync(0xffffffffu, bi, src);
        }
        if (l == 0) ot[t] = (float)tag;
    }
}

// ---------------- launch ---------------------------------------------
extern "C" void kernel_launch(void* const* d_in, const int* in_sizes, int n_in,
                              void* d_out, int out_size) {
    const float* emis  = (const float*)d_in[0];
    const int*   tags  = (const int*)d_in[1];
    const int*   mask  = (const int*)d_in[2];
    const float* trans = (const float*)d_in[3];
    float* out = (float*)d_out;

    float* out_ll    = out;
    float* out_trans = out + BB;
    float* out_tags  = out + BB + NN * NN;

    cudaFuncSetAttribute(k_traceback, cudaFuncAttributeMaxDynamicSharedMemorySize,
                         NN * NN * (int)sizeof(float));

    k_prep<<<(NN * NN + 255) / 256, 256>>>(trans, out_trans);
    k_score<<<BB, 256>>>(emis, tags, mask, trans);
    k_recur<<<2 * BB, 128>>>(emis, mask, trans, out_ll);
    k_traceback<<<BB / 8, 256, NN * NN * (int)sizeof(float)>>>(mask, out_tags);
}